// round 3
// baseline (speedup 1.0000x reference)
#include <cuda_runtime.h>
#include <math.h>

#define BB 64
#define QQ 900
#define GG 100
#define NC 10
#define NC1 11

// -------- device scratch (static: no allocation) --------
__device__ float  g_costT[BB * GG * QQ];   // transposed cost: [b][gt_row_k][q]
__device__ int    g_vlist[BB * GG];        // valid gt indices per batch
__device__ int    g_nvalid[BB];
__device__ int    g_match[BB * QQ];        // per query: matched gt index or -1
__device__ int    g_nmatched;
__device__ double g_cls_num;
__device__ double g_cls_den;
__device__ double g_l1;
__device__ double g_gl;

__global__ void init_kernel() {
    if (threadIdx.x == 0) {
        g_nmatched = 0;
        g_cls_num = 0.0;
        g_cls_den = 0.0;
        g_l1 = 0.0;
        g_gl = 0.0;
    }
}

// one block per batch: compact valid gt indices
__global__ void prep_kernel(const int* __restrict__ gt_classes) {
    int b = blockIdx.x;
    if (threadIdx.x == 0) {
        int n = 0;
        for (int g = 0; g < GG; g++) {
            if (gt_classes[b * GG + g] >= 0) g_vlist[b * GG + n++] = g;
        }
        g_nvalid[b] = n;
    }
}

// cost[b][q][k] -> stored transposed as g_costT[(b*GG + k)*QQ + q]
__global__ void cost_kernel(const float* __restrict__ logits,
                            const float* __restrict__ pboxes,
                            const int*   __restrict__ gtc,
                            const float* __restrict__ gboxes) {
    int b = blockIdx.y;
    int q = blockIdx.x * blockDim.x + threadIdx.x;

    __shared__ float sgx0[GG], sgy0[GG], sgx1[GG], sgy1[GG], sga[GG];
    __shared__ float sgcx[GG], sgcy[GG], sgw[GG], sgh[GG];
    __shared__ int   scls[GG];
    __shared__ int   sn;

    if (threadIdx.x == 0) sn = g_nvalid[b];
    __syncthreads();
    int n = sn;

    for (int k = threadIdx.x; k < n; k += blockDim.x) {
        int gi = g_vlist[b * GG + k];
        const float* gb = gboxes + ((size_t)(b * GG + gi)) * 4;
        float cx = gb[0], cy = gb[1], w = gb[2], h = gb[3];
        float x0 = cx - w * 0.5f, y0 = cy - h * 0.5f;
        float x1 = cx + w * 0.5f, y1 = cy + h * 0.5f;
        sgx0[k] = x0; sgy0[k] = y0; sgx1[k] = x1; sgy1[k] = y1;
        sga[k] = fmaxf(x1 - x0, 0.f) * fmaxf(y1 - y0, 0.f);
        sgcx[k] = cx; sgcy[k] = cy; sgw[k] = w; sgh[k] = h;
        int c = gtc[b * GG + gi];
        scls[k] = (c < 0) ? 0 : (c > NC - 1 ? NC - 1 : c);
    }
    __syncthreads();
    if (q >= QQ) return;

    // softmax over NC1 logits
    const float* lg = logits + ((size_t)(b * QQ + q)) * NC1;
    float e[NC1];
    float mx = lg[0];
#pragma unroll
    for (int c = 1; c < NC1; c++) mx = fmaxf(mx, lg[c]);
    float s = 0.f;
#pragma unroll
    for (int c = 0; c < NC1; c++) { e[c] = expf(lg[c] - mx); s += e[c]; }
    float inv_s = 1.0f / s;

    const float* pb = pboxes + ((size_t)(b * QQ + q)) * 4;
    float pcx = pb[0], pcy = pb[1], pw = pb[2], ph = pb[3];
    float px0 = pcx - pw * 0.5f, py0 = pcy - ph * 0.5f;
    float px1 = pcx + pw * 0.5f, py1 = pcy + ph * 0.5f;
    float pa = fmaxf(px1 - px0, 0.f) * fmaxf(py1 - py0, 0.f);

    float* outc = g_costT + (size_t)b * GG * QQ + q;
    for (int k = 0; k < n; k++) {
        float clsc = -(e[scls[k]] * inv_s);
        float l1 = fabsf(pcx - sgcx[k]) + fabsf(pcy - sgcy[k]) +
                   fabsf(pw - sgw[k]) + fabsf(ph - sgh[k]);
        float gx0 = sgx0[k], gy0 = sgy0[k], gx1 = sgx1[k], gy1 = sgy1[k];
        float ltx = fmaxf(px0, gx0), lty = fmaxf(py0, gy0);
        float rbx = fminf(px1, gx1), rby = fminf(py1, gy1);
        float iw = fmaxf(rbx - ltx, 0.f), ih = fmaxf(rby - lty, 0.f);
        float inter = iw * ih;
        float uni = pa + sga[k] - inter;
        float iou = inter / fmaxf(uni, 1e-6f);
        float ex0 = fminf(px0, gx0), ey0 = fminf(py0, gy0);
        float ex1 = fmaxf(px1, gx1), ey1 = fmaxf(py1, gy1);
        float ew = fmaxf(ex1 - ex0, 0.f), eh = fmaxf(ey1 - ey0, 0.f);
        float enc = ew * eh;
        float giou = iou - (enc - uni) / fmaxf(enc, 1e-6f);
        outc[(size_t)k * QQ] = 2.0f * clsc + 5.0f * l1 - 2.0f * giou;
    }
}

// Jonker-Volgenant, single-warp per batch, cumulative-offset duals.
// Exactly order-preserving vs reference float64 JV:
//   stored minv' = true_minv + D_now  (same additive offset for cur' too),
//   so comparisons/argmin/delta decisions are identical; duals committed
//   once per augmentation as (D_final - D_at_use).
__global__ void __launch_bounds__(32) jv_kernel() {
    const int b = blockIdx.x;
    const int lane = threadIdx.x;
    const int m = QQ;
    const int n = g_nvalid[b];

    __shared__ double sv[QQ + 1];     // committed v duals
    __shared__ double sminv[QQ + 1];  // offset-shifted minv'
    __shared__ double su[GG + 2];     // committed u duals
    __shared__ double sDused[QQ + 1];
    __shared__ int    sway[QQ + 1];
    __shared__ int    sp[QQ + 1];
    __shared__ int    susedList[QQ + 1];
    __shared__ unsigned char sused[QQ + 1];

    for (int j = lane; j <= m; j += 32) { sv[j] = 0.0; sp[j] = 0; }
    for (int i = lane; i < GG + 2; i += 32) su[i] = 0.0;
    __syncwarp();

    const float* Cbase = g_costT + (size_t)b * GG * QQ;

    for (int i = 1; i <= n; i++) {
        for (int j = lane; j <= m; j += 32) {
            sminv[j] = 1e300;
            sway[j] = 0;
            sused[j] = 0;
        }
        if (lane == 0) sp[0] = i;
        __syncwarp();

        int j0 = 0;        // uniform registers across the warp
        double D = 0.0;
        int cnt = 0;

        while (true) {
            const int i0 = sp[j0];              // shared broadcast read
            const double ueff = su[i0] - D;     // u[i0] - D_enter(i0)
            if (lane == 0) {
                sused[j0] = 1;
                susedList[cnt] = j0;
                sDused[cnt] = D;
            }
            cnt++;
            __syncwarp();

            const float* __restrict__ Crow = Cbase + (size_t)(i0 - 1) * QQ;
            double lmin = 1e300;
            int lj = m + 1;
            for (int j = 1 + lane; j <= m; j += 32) {
                if (!sused[j]) {
                    double cur = (double)__ldg(&Crow[j - 1]) - ueff - sv[j];
                    double mv = sminv[j];
                    if (cur < mv) { mv = cur; sminv[j] = cur; sway[j] = j0; }
                    if (mv < lmin) { lmin = mv; lj = j; }
                }
            }
            // warp (value, index) min-reduce; tie -> smaller index (== np.argmin)
#pragma unroll
            for (int off = 16; off; off >>= 1) {
                double ov = __shfl_down_sync(0xffffffffu, lmin, off);
                int    oi = __shfl_down_sync(0xffffffffu, lj, off);
                if (ov < lmin || (ov == lmin && oi < lj)) { lmin = ov; lj = oi; }
            }
            D  = __shfl_sync(0xffffffffu, lmin, 0);  // new cumulative D = min minv'
            j0 = __shfl_sync(0xffffffffu, lj, 0);
            if (sp[j0] == 0) break;
        }

        if (lane == 0) {
            // commit duals over used columns
            for (int t = 0; t < cnt; t++) {
                int j = susedList[t];
                double dd = D - sDused[t];
                su[sp[j]] += dd;
                if (j != 0) sv[j] -= dd;
            }
            // augment along alternating tree
            int jj = j0;
            while (jj != 0) {
                int jn = sway[jj];
                sp[jj] = sp[jn];
                jj = jn;
            }
        }
        __syncwarp();

        // prefetch next outer row (one 128B line per lane) to hide L2 latency
        if (i < n && lane < (QQ + 31) / 32) {
            const float* Cnext = Cbase + (size_t)i * QQ + lane * 32;
            asm volatile("prefetch.global.L1 [%0];" :: "l"(Cnext));
        }
    }

    for (int j = lane + 1; j <= m; j += 32) {
        int r = sp[j];
        g_match[b * QQ + (j - 1)] = (r > 0) ? g_vlist[b * GG + (r - 1)] : -1;
    }
    if (lane == 0) atomicAdd(&g_nmatched, n);
}

__global__ void loss_kernel(const float* __restrict__ logits,
                            const float* __restrict__ pboxes,
                            const int*   __restrict__ gtc,
                            const float* __restrict__ gboxes) {
    int idx = blockIdx.x * blockDim.x + threadIdx.x;
    double nllw = 0.0, wsum = 0.0, l1acc = 0.0, glacc = 0.0;

    if (idx < BB * QQ) {
        int b = idx / QQ;
        const float* lg = logits + (size_t)idx * NC1;
        float mx = lg[0];
#pragma unroll
        for (int c = 1; c < NC1; c++) mx = fmaxf(mx, lg[c]);
        float s = 0.f;
#pragma unroll
        for (int c = 0; c < NC1; c++) s += expf(lg[c] - mx);
        float logZ = mx + logf(s);

        int mg = g_match[idx];
        int t = (mg >= 0) ? gtc[b * GG + mg] : NC;
        float logp = lg[t] - logZ;
        float wt = (t == NC) ? 0.1f : 1.0f;
        nllw = (double)(wt * (-logp));
        wsum = (double)wt;

        if (mg >= 0) {
            const float* pb = pboxes + (size_t)idx * 4;
            const float* gb = gboxes + ((size_t)(b * GG + mg)) * 4;
            float pcx = pb[0], pcy = pb[1], pw = pb[2], ph = pb[3];
            float gcx = gb[0], gcy = gb[1], gw = gb[2], gh = gb[3];
            l1acc = (double)(fabsf(pcx - gcx) + fabsf(pcy - gcy) +
                             fabsf(pw - gw) + fabsf(ph - gh));
            float px0 = pcx - pw * 0.5f, py0 = pcy - ph * 0.5f;
            float px1 = pcx + pw * 0.5f, py1 = pcy + ph * 0.5f;
            float gx0 = gcx - gw * 0.5f, gy0 = gcy - gh * 0.5f;
            float gx1 = gcx + gw * 0.5f, gy1 = gcy + gh * 0.5f;
            float pa = fmaxf(px1 - px0, 0.f) * fmaxf(py1 - py0, 0.f);
            float ga = fmaxf(gx1 - gx0, 0.f) * fmaxf(gy1 - gy0, 0.f);
            float ltx = fmaxf(px0, gx0), lty = fmaxf(py0, gy0);
            float rbx = fminf(px1, gx1), rby = fminf(py1, gy1);
            float iw = fmaxf(rbx - ltx, 0.f), ih = fmaxf(rby - lty, 0.f);
            float inter = iw * ih;
            float uni = pa + ga - inter;
            float iou = inter / fmaxf(uni, 1e-6f);
            float ex0 = fminf(px0, gx0), ey0 = fminf(py0, gy0);
            float ex1 = fmaxf(px1, gx1), ey1 = fmaxf(py1, gy1);
            float ew = fmaxf(ex1 - ex0, 0.f), eh = fmaxf(ey1 - ey0, 0.f);
            float enc = ew * eh;
            float giou = iou - (enc - uni) / fmaxf(enc, 1e-6f);
            glacc = (double)(1.0f - giou);
        }
    }

    __shared__ double s1[256], s2[256], s3[256], s4[256];
    int tid = threadIdx.x;
    s1[tid] = nllw; s2[tid] = wsum; s3[tid] = l1acc; s4[tid] = glacc;
    __syncthreads();
#pragma unroll
    for (int s = 128; s > 0; s >>= 1) {
        if (tid < s) {
            s1[tid] += s1[tid + s];
            s2[tid] += s2[tid + s];
            s3[tid] += s3[tid + s];
            s4[tid] += s4[tid + s];
        }
        __syncthreads();
    }
    if (tid == 0) {
        atomicAdd(&g_cls_num, s1[0]);
        atomicAdd(&g_cls_den, s2[0]);
        atomicAdd(&g_l1, s3[0]);
        atomicAdd(&g_gl, s4[0]);
    }
}

__global__ void finalize_kernel(float* __restrict__ out) {
    if (threadIdx.x == 0) {
        int nm = g_nmatched;
        if (nm < 1) nm = 1;
        double nmd = (double)nm;
        double cls = g_cls_num / g_cls_den;
        out[0] = (float)(2.0 * cls + 5.0 * g_l1 / nmd + 2.0 * g_gl / nmd);
    }
}

extern "C" void kernel_launch(void* const* d_in, const int* in_sizes, int n_in,
                              void* d_out, int out_size) {
    const float* pred_logits = (const float*)d_in[0];
    const float* pred_boxes  = (const float*)d_in[1];
    const int*   gt_classes  = (const int*)d_in[2];
    const float* gt_boxes    = (const float*)d_in[3];
    float* out = (float*)d_out;

    init_kernel<<<1, 32>>>();
    prep_kernel<<<BB, 32>>>(gt_classes);

    dim3 cgrid((QQ + 127) / 128, BB);
    cost_kernel<<<cgrid, 128>>>(pred_logits, pred_boxes, gt_classes, gt_boxes);

    jv_kernel<<<BB, 32>>>();

    int total = BB * QQ;
    loss_kernel<<<(total + 255) / 256, 256>>>(pred_logits, pred_boxes,
                                              gt_classes, gt_boxes);
    finalize_kernel<<<1, 32>>>(out);
}

// round 4
// speedup vs baseline: 5.9839x; 5.9839x over previous
#include <cuda_runtime.h>
#include <math.h>

#define BB 64
#define QQ 900
#define GG 100
#define NC 10
#define NC1 11
#define SLOTS 29   // ceil(900/32)

// -------- device scratch (static: no allocation) --------
__device__ float  g_costT[BB * GG * QQ];   // transposed cost: [b][gt_row_k][q]
__device__ int    g_vlist[BB * GG];        // valid gt indices per batch
__device__ int    g_nvalid[BB];
__device__ int    g_match[BB * QQ];        // per query: matched gt index or -1
__device__ int    g_nmatched;
__device__ double g_cls_num;
__device__ double g_cls_den;
__device__ double g_l1;
__device__ double g_gl;

__global__ void init_kernel() {
    if (threadIdx.x == 0) {
        g_nmatched = 0;
        g_cls_num = 0.0;
        g_cls_den = 0.0;
        g_l1 = 0.0;
        g_gl = 0.0;
    }
}

// one block per batch: compact valid gt indices
__global__ void prep_kernel(const int* __restrict__ gt_classes) {
    int b = blockIdx.x;
    if (threadIdx.x == 0) {
        int n = 0;
        for (int g = 0; g < GG; g++) {
            if (gt_classes[b * GG + g] >= 0) g_vlist[b * GG + n++] = g;
        }
        g_nvalid[b] = n;
    }
}

// cost[b][q][k] -> stored transposed as g_costT[(b*GG + k)*QQ + q]
__global__ void cost_kernel(const float* __restrict__ logits,
                            const float* __restrict__ pboxes,
                            const int*   __restrict__ gtc,
                            const float* __restrict__ gboxes) {
    int b = blockIdx.y;
    int q = blockIdx.x * blockDim.x + threadIdx.x;

    __shared__ float sgx0[GG], sgy0[GG], sgx1[GG], sgy1[GG], sga[GG];
    __shared__ float sgcx[GG], sgcy[GG], sgw[GG], sgh[GG];
    __shared__ int   scls[GG];
    __shared__ int   sn;

    if (threadIdx.x == 0) sn = g_nvalid[b];
    __syncthreads();
    int n = sn;

    for (int k = threadIdx.x; k < n; k += blockDim.x) {
        int gi = g_vlist[b * GG + k];
        const float* gb = gboxes + ((size_t)(b * GG + gi)) * 4;
        float cx = gb[0], cy = gb[1], w = gb[2], h = gb[3];
        float x0 = cx - w * 0.5f, y0 = cy - h * 0.5f;
        float x1 = cx + w * 0.5f, y1 = cy + h * 0.5f;
        sgx0[k] = x0; sgy0[k] = y0; sgx1[k] = x1; sgy1[k] = y1;
        sga[k] = fmaxf(x1 - x0, 0.f) * fmaxf(y1 - y0, 0.f);
        sgcx[k] = cx; sgcy[k] = cy; sgw[k] = w; sgh[k] = h;
        int c = gtc[b * GG + gi];
        scls[k] = (c < 0) ? 0 : (c > NC - 1 ? NC - 1 : c);
    }
    __syncthreads();
    if (q >= QQ) return;

    // softmax over NC1 logits
    const float* lg = logits + ((size_t)(b * QQ + q)) * NC1;
    float e[NC1];
    float mx = lg[0];
#pragma unroll
    for (int c = 1; c < NC1; c++) mx = fmaxf(mx, lg[c]);
    float s = 0.f;
#pragma unroll
    for (int c = 0; c < NC1; c++) { e[c] = expf(lg[c] - mx); s += e[c]; }
    float inv_s = 1.0f / s;

    const float* pb = pboxes + ((size_t)(b * QQ + q)) * 4;
    float pcx = pb[0], pcy = pb[1], pw = pb[2], ph = pb[3];
    float px0 = pcx - pw * 0.5f, py0 = pcy - ph * 0.5f;
    float px1 = pcx + pw * 0.5f, py1 = pcy + ph * 0.5f;
    float pa = fmaxf(px1 - px0, 0.f) * fmaxf(py1 - py0, 0.f);

    float* outc = g_costT + (size_t)b * GG * QQ + q;
    for (int k = 0; k < n; k++) {
        float clsc = -(e[scls[k]] * inv_s);
        float l1 = fabsf(pcx - sgcx[k]) + fabsf(pcy - sgcy[k]) +
                   fabsf(pw - sgw[k]) + fabsf(ph - sgh[k]);
        float gx0 = sgx0[k], gy0 = sgy0[k], gx1 = sgx1[k], gy1 = sgy1[k];
        float ltx = fmaxf(px0, gx0), lty = fmaxf(py0, gy0);
        float rbx = fminf(px1, gx1), rby = fminf(py1, gy1);
        float iw = fmaxf(rbx - ltx, 0.f), ih = fmaxf(rby - lty, 0.f);
        float inter = iw * ih;
        float uni = pa + sga[k] - inter;
        float iou = inter / fmaxf(uni, 1e-6f);
        float ex0 = fminf(px0, gx0), ey0 = fminf(py0, gy0);
        float ex1 = fmaxf(px1, gx1), ey1 = fmaxf(py1, gy1);
        float ew = fmaxf(ex1 - ex0, 0.f), eh = fmaxf(ey1 - ey0, 0.f);
        float enc = ew * eh;
        float giou = iou - (enc - uni) / fmaxf(enc, 1e-6f);
        outc[(size_t)k * QQ] = 2.0f * clsc + 5.0f * l1 - 2.0f * giou;
    }
}

// Jonker-Volgenant, 1 warp per batch, float32, cumulative-offset duals.
// Column j is owned by lane (j-1)&31. svm[j] = {v_j, minv'_j}; "used" is
// encoded as minv' = NaN (NaN comparisons exclude it from update & argmin).
// No __syncwarp needed inside the phase loop: each lane reads/writes only
// its own columns' svm; cross-lane values move via shuffles.
__global__ void __launch_bounds__(32) jv_kernel() {
    const int b = blockIdx.x;
    const int lane = threadIdx.x;
    const int m = QQ;
    const int n = g_nvalid[b];
    const float FNAN = __int_as_float(0x7fc00000);

    __shared__ float2 svm[QQ + 1];   // .x = committed v dual, .y = minv'
    __shared__ float  su[GG + 2];    // committed u duals
    __shared__ float  sDused[QQ + 1];
    __shared__ int    sway[QQ + 1];
    __shared__ int    sp[QQ + 1];
    __shared__ int    susedList[QQ + 1];

    for (int j = lane; j <= m; j += 32) { svm[j] = make_float2(0.f, 1e30f); sp[j] = 0; }
    for (int i = lane; i < GG + 2; i += 32) su[i] = 0.0f;
    __syncwarp();

    const float* Cbase = g_costT + (size_t)b * GG * QQ;

    for (int i = 1; i <= n; i++) {
        // reset minv' for owned columns (v persists)
#pragma unroll
        for (int s = 0; s < SLOTS; s++) {
            int j = 1 + lane + (s << 5);
            if (j <= m) svm[j].y = 1e30f;
        }
        if (lane == 0) sp[0] = i;
        __syncwarp();

        int j0 = 0;       // uniform across warp
        float D = 0.0f;
        int cnt = 0;

        while (true) {
            const int i0 = sp[j0];            // uniform LDS broadcast
            const float ueff = su[i0] - D;
            if (lane == 0) { susedList[cnt] = j0; sDused[cnt] = D; }
            if (j0 > 0 && (((j0 - 1) & 31) == lane)) svm[j0].y = FNAN; // mark used (owner lane)
            cnt++;

            const float* __restrict__ Crow = Cbase + (size_t)(i0 - 1) * QQ;

            // (a) batched loads: full MLP, one L2 round trip
            float c[SLOTS];
#pragma unroll
            for (int s = 0; s < SLOTS; s++) {
                int j = 1 + lane + (s << 5);
                c[s] = (j <= m) ? __ldg(&Crow[j - 1]) : 1e30f;
            }

            // (b) compute pass against owned shared state
            float lmin = 1e30f;
            int lj = m + 1;
#pragma unroll
            for (int s = 0; s < SLOTS; s++) {
                int j = 1 + lane + (s << 5);
                if (j <= m) {
                    float2 vm = svm[j];
                    float cur = c[s] - ueff - vm.x;
                    float mv = vm.y;               // NaN if used
                    if (cur < mv) {                 // false when mv is NaN
                        mv = cur;
                        svm[j].y = cur;
                        sway[j] = j0;
                    }
                    if (mv < lmin) { lmin = mv; lj = j; }  // false when NaN
                }
            }
            // warp (value, index) min-reduce; tie -> smaller index (== np.argmin)
#pragma unroll
            for (int off = 16; off; off >>= 1) {
                float ov = __shfl_down_sync(0xffffffffu, lmin, off);
                int   oi = __shfl_down_sync(0xffffffffu, lj, off);
                if (ov < lmin || (ov == lmin && oi < lj)) { lmin = ov; lj = oi; }
            }
            D  = __shfl_sync(0xffffffffu, lmin, 0);  // new cumulative offset
            j0 = __shfl_sync(0xffffffffu, lj, 0);
            if (sp[j0] == 0) break;
        }

        // commit duals over used columns (distinct rows & cols -> race-free)
        __syncwarp();
        for (int t = lane; t < cnt; t += 32) {
            int j = susedList[t];
            float dd = D - sDused[t];
            su[sp[j]] += dd;
            if (j != 0) svm[j].x -= dd;
        }
        __syncwarp();
        if (lane == 0) {
            // augment along alternating tree
            int jj = j0;
            while (jj != 0) {
                int jn = sway[jj];
                sp[jj] = sp[jn];
                jj = jn;
            }
        }
        __syncwarp();

        // prefetch next outer row to L1 while bookkeeping settles
        if (i < n) {
            const float* Cnext = Cbase + (size_t)i * QQ + lane * 32;
            if (lane * 32 < QQ)
                asm volatile("prefetch.global.L1 [%0];" :: "l"(Cnext));
        }
    }

    for (int j = lane + 1; j <= m; j += 32) {
        int r = sp[j];
        g_match[b * QQ + (j - 1)] = (r > 0) ? g_vlist[b * GG + (r - 1)] : -1;
    }
    if (lane == 0) atomicAdd(&g_nmatched, n);
}

__global__ void loss_kernel(const float* __restrict__ logits,
                            const float* __restrict__ pboxes,
                            const int*   __restrict__ gtc,
                            const float* __restrict__ gboxes) {
    int idx = blockIdx.x * blockDim.x + threadIdx.x;
    double nllw = 0.0, wsum = 0.0, l1acc = 0.0, glacc = 0.0;

    if (idx < BB * QQ) {
        int b = idx / QQ;
        const float* lg = logits + (size_t)idx * NC1;
        float mx = lg[0];
#pragma unroll
        for (int c = 1; c < NC1; c++) mx = fmaxf(mx, lg[c]);
        float s = 0.f;
#pragma unroll
        for (int c = 0; c < NC1; c++) s += expf(lg[c] - mx);
        float logZ = mx + logf(s);

        int mg = g_match[idx];
        int t = (mg >= 0) ? gtc[b * GG + mg] : NC;
        float logp = lg[t] - logZ;
        float wt = (t == NC) ? 0.1f : 1.0f;
        nllw = (double)(wt * (-logp));
        wsum = (double)wt;

        if (mg >= 0) {
            const float* pb = pboxes + (size_t)idx * 4;
            const float* gb = gboxes + ((size_t)(b * GG + mg)) * 4;
            float pcx = pb[0], pcy = pb[1], pw = pb[2], ph = pb[3];
            float gcx = gb[0], gcy = gb[1], gw = gb[2], gh = gb[3];
            l1acc = (double)(fabsf(pcx - gcx) + fabsf(pcy - gcy) +
                             fabsf(pw - gw) + fabsf(ph - gh));
            float px0 = pcx - pw * 0.5f, py0 = pcy - ph * 0.5f;
            float px1 = pcx + pw * 0.5f, py1 = pcy + ph * 0.5f;
            float gx0 = gcx - gw * 0.5f, gy0 = gcy - gh * 0.5f;
            float gx1 = gcx + gw * 0.5f, gy1 = gcy + gh * 0.5f;
            float pa = fmaxf(px1 - px0, 0.f) * fmaxf(py1 - py0, 0.f);
            float ga = fmaxf(gx1 - gx0, 0.f) * fmaxf(gy1 - gy0, 0.f);
            float ltx = fmaxf(px0, gx0), lty = fmaxf(py0, gy0);
            float rbx = fminf(px1, gx1), rby = fminf(py1, gy1);
            float iw = fmaxf(rbx - ltx, 0.f), ih = fmaxf(rby - lty, 0.f);
            float inter = iw * ih;
            float uni = pa + ga - inter;
            float iou = inter / fmaxf(uni, 1e-6f);
            float ex0 = fminf(px0, gx0), ey0 = fminf(py0, gy0);
            float ex1 = fmaxf(px1, gx1), ey1 = fmaxf(py1, gy1);
            float ew = fmaxf(ex1 - ex0, 0.f), eh = fmaxf(ey1 - ey0, 0.f);
            float enc = ew * eh;
            float giou = iou - (enc - uni) / fmaxf(enc, 1e-6f);
            glacc = (double)(1.0f - giou);
        }
    }

    __shared__ double s1[256], s2[256], s3[256], s4[256];
    int tid = threadIdx.x;
    s1[tid] = nllw; s2[tid] = wsum; s3[tid] = l1acc; s4[tid] = glacc;
    __syncthreads();
#pragma unroll
    for (int s = 128; s > 0; s >>= 1) {
        if (tid < s) {
            s1[tid] += s1[tid + s];
            s2[tid] += s2[tid + s];
            s3[tid] += s3[tid + s];
            s4[tid] += s4[tid + s];
        }
        __syncthreads();
    }
    if (tid == 0) {
        atomicAdd(&g_cls_num, s1[0]);
        atomicAdd(&g_cls_den, s2[0]);
        atomicAdd(&g_l1, s3[0]);
        atomicAdd(&g_gl, s4[0]);
    }
}

__global__ void finalize_kernel(float* __restrict__ out) {
    if (threadIdx.x == 0) {
        int nm = g_nmatched;
        if (nm < 1) nm = 1;
        double nmd = (double)nm;
        double cls = g_cls_num / g_cls_den;
        out[0] = (float)(2.0 * cls + 5.0 * g_l1 / nmd + 2.0 * g_gl / nmd);
    }
}

extern "C" void kernel_launch(void* const* d_in, const int* in_sizes, int n_in,
                              void* d_out, int out_size) {
    const float* pred_logits = (const float*)d_in[0];
    const float* pred_boxes  = (const float*)d_in[1];
    const int*   gt_classes  = (const int*)d_in[2];
    const float* gt_boxes    = (const float*)d_in[3];
    float* out = (float*)d_out;

    init_kernel<<<1, 32>>>();
    prep_kernel<<<BB, 32>>>(gt_classes);

    dim3 cgrid((QQ + 127) / 128, BB);
    cost_kernel<<<cgrid, 128>>>(pred_logits, pred_boxes, gt_classes, gt_boxes);

    jv_kernel<<<BB, 32>>>();

    int total = BB * QQ;
    loss_kernel<<<(total + 255) / 256, 256>>>(pred_logits, pred_boxes,
                                              gt_classes, gt_boxes);
    finalize_kernel<<<1, 32>>>(out);
}

// round 5
// speedup vs baseline: 14.9504x; 2.4984x over previous
#include <cuda_runtime.h>
#include <math.h>

#define BB 64
#define QQ 900
#define GG 100
#define NC 10
#define NC1 11
#define SLOTS 29   // ceil(900/32)

// -------- device scratch (static: no allocation) --------
__device__ float  g_costT[BB * GG * QQ];   // transposed cost: [b][gt_row_k][q]
__device__ int    g_vlist[BB * GG];        // valid gt indices per batch
__device__ int    g_nvalid[BB];
__device__ float  g_rowminval[BB * GG];    // min over q of cost row
__device__ int    g_rowminidx[BB * GG];    // argmin (smallest q on ties)
__device__ int    g_match[BB * QQ];        // per query: matched gt index or -1
__device__ int    g_nmatched;
__device__ double g_cls_num;
__device__ double g_cls_den;
__device__ double g_l1;
__device__ double g_gl;

__global__ void init_kernel() {
    if (threadIdx.x == 0) {
        g_nmatched = 0;
        g_cls_num = 0.0;
        g_cls_den = 0.0;
        g_l1 = 0.0;
        g_gl = 0.0;
    }
}

// one block per batch: compact valid gt indices
__global__ void prep_kernel(const int* __restrict__ gt_classes) {
    int b = blockIdx.x;
    if (threadIdx.x == 0) {
        int n = 0;
        for (int g = 0; g < GG; g++) {
            if (gt_classes[b * GG + g] >= 0) g_vlist[b * GG + n++] = g;
        }
        g_nvalid[b] = n;
    }
}

// cost[b][q][k] -> stored transposed as g_costT[(b*GG + k)*QQ + q]
__global__ void cost_kernel(const float* __restrict__ logits,
                            const float* __restrict__ pboxes,
                            const int*   __restrict__ gtc,
                            const float* __restrict__ gboxes) {
    int b = blockIdx.y;
    int q = blockIdx.x * blockDim.x + threadIdx.x;

    __shared__ float sgx0[GG], sgy0[GG], sgx1[GG], sgy1[GG], sga[GG];
    __shared__ float sgcx[GG], sgcy[GG], sgw[GG], sgh[GG];
    __shared__ int   scls[GG];
    __shared__ int   sn;

    if (threadIdx.x == 0) sn = g_nvalid[b];
    __syncthreads();
    int n = sn;

    for (int k = threadIdx.x; k < n; k += blockDim.x) {
        int gi = g_vlist[b * GG + k];
        const float* gb = gboxes + ((size_t)(b * GG + gi)) * 4;
        float cx = gb[0], cy = gb[1], w = gb[2], h = gb[3];
        float x0 = cx - w * 0.5f, y0 = cy - h * 0.5f;
        float x1 = cx + w * 0.5f, y1 = cy + h * 0.5f;
        sgx0[k] = x0; sgy0[k] = y0; sgx1[k] = x1; sgy1[k] = y1;
        sga[k] = fmaxf(x1 - x0, 0.f) * fmaxf(y1 - y0, 0.f);
        sgcx[k] = cx; sgcy[k] = cy; sgw[k] = w; sgh[k] = h;
        int c = gtc[b * GG + gi];
        scls[k] = (c < 0) ? 0 : (c > NC - 1 ? NC - 1 : c);
    }
    __syncthreads();
    if (q >= QQ) return;

    // softmax over NC1 logits
    const float* lg = logits + ((size_t)(b * QQ + q)) * NC1;
    float e[NC1];
    float mx = lg[0];
#pragma unroll
    for (int c = 1; c < NC1; c++) mx = fmaxf(mx, lg[c]);
    float s = 0.f;
#pragma unroll
    for (int c = 0; c < NC1; c++) { e[c] = expf(lg[c] - mx); s += e[c]; }
    float inv_s = 1.0f / s;

    const float* pb = pboxes + ((size_t)(b * QQ + q)) * 4;
    float pcx = pb[0], pcy = pb[1], pw = pb[2], ph = pb[3];
    float px0 = pcx - pw * 0.5f, py0 = pcy - ph * 0.5f;
    float px1 = pcx + pw * 0.5f, py1 = pcy + ph * 0.5f;
    float pa = fmaxf(px1 - px0, 0.f) * fmaxf(py1 - py0, 0.f);

    float* outc = g_costT + (size_t)b * GG * QQ + q;
    for (int k = 0; k < n; k++) {
        float clsc = -(e[scls[k]] * inv_s);
        float l1 = fabsf(pcx - sgcx[k]) + fabsf(pcy - sgcy[k]) +
                   fabsf(pw - sgw[k]) + fabsf(ph - sgh[k]);
        float gx0 = sgx0[k], gy0 = sgy0[k], gx1 = sgx1[k], gy1 = sgy1[k];
        float ltx = fmaxf(px0, gx0), lty = fmaxf(py0, gy0);
        float rbx = fminf(px1, gx1), rby = fminf(py1, gy1);
        float iw = fmaxf(rbx - ltx, 0.f), ih = fmaxf(rby - lty, 0.f);
        float inter = iw * ih;
        float uni = pa + sga[k] - inter;
        float iou = inter / fmaxf(uni, 1e-6f);
        float ex0 = fminf(px0, gx0), ey0 = fminf(py0, gy0);
        float ex1 = fmaxf(px1, gx1), ey1 = fmaxf(py1, gy1);
        float ew = fmaxf(ex1 - ex0, 0.f), eh = fmaxf(ey1 - ey0, 0.f);
        float enc = ew * eh;
        float giou = iou - (enc - uni) / fmaxf(enc, 1e-6f);
        outc[(size_t)k * QQ] = 2.0f * clsc + 5.0f * l1 - 2.0f * giou;
    }
}

// ordered-uint key: monotone map float -> uint32 (handles negatives)
__device__ __forceinline__ unsigned int fkey(float f) {
    unsigned int b = __float_as_uint(f);
    return (b & 0x80000000u) ? ~b : (b | 0x80000000u);
}

// one block per (row k, batch b): min + argmin over the 900-entry cost row
__global__ void __launch_bounds__(256) rowmin_kernel() {
    const int k = blockIdx.x;
    const int b = blockIdx.y;
    if (k >= g_nvalid[b]) return;

    const float* __restrict__ Crow = g_costT + ((size_t)(b * GG + k)) * QQ;
    const int tid = threadIdx.x;

    unsigned long long best = 0xFFFFFFFFFFFFFFFFull;
    for (int q = tid; q < QQ; q += 256) {
        unsigned long long pk = ((unsigned long long)fkey(Crow[q]) << 32) | (unsigned int)q;
        if (pk < best) best = pk;
    }
#pragma unroll
    for (int off = 16; off; off >>= 1) {
        unsigned long long o = __shfl_down_sync(0xffffffffu, best, off);
        if (o < best) best = o;
    }
    __shared__ unsigned long long sw[8];
    if ((tid & 31) == 0) sw[tid >> 5] = best;
    __syncthreads();
    if (tid == 0) {
        unsigned long long bb = sw[0];
#pragma unroll
        for (int w = 1; w < 8; w++) if (sw[w] < bb) bb = sw[w];
        int q = (int)(bb & 0xFFFFFFFFull);
        g_rowminval[b * GG + k] = Crow[q];
        g_rowminidx[b * GG + k] = q;
    }
}

// Warm-started Jonker-Volgenant, 1 warp per batch, float32 duals.
//  init: u[i] = row min (feasible with v=0), greedy-assign rows to their
//  argmin column when free (zero reduced cost -> complementary slackness).
//  Remaining rows solved by exact shortest-augmenting-path (same as before);
//  unique optimum -> identical assignment to the reference solver.
__global__ void __launch_bounds__(32) jv_kernel() {
    const int b = blockIdx.x;
    const int lane = threadIdx.x;
    const int m = QQ;
    const int n = g_nvalid[b];
    const float FNAN = __int_as_float(0x7fc00000);

    __shared__ float2 svm[QQ + 1];   // .x = committed v dual, .y = minv'
    __shared__ float  su[GG + 2];    // committed u duals
    __shared__ float  sDused[QQ + 1];
    __shared__ int    sway[QQ + 1];
    __shared__ int    sp[QQ + 1];
    __shared__ int    susedList[QQ + 1];
    __shared__ int    sfree[GG + 1];
    __shared__ int    snfree;

    for (int j = lane; j <= m; j += 32) { svm[j] = make_float2(0.f, 1e30f); sp[j] = 0; }
    for (int i = lane; i < GG + 2; i += 32) su[i] = 0.0f;
    __syncwarp();

    // row reduction + greedy assignment (serial, tiny)
    if (lane == 0) {
        int nf = 0;
        for (int i = 1; i <= n; i++) {
            su[i] = g_rowminval[b * GG + (i - 1)];
            int jmin = g_rowminidx[b * GG + (i - 1)] + 1;
            if (sp[jmin] == 0) sp[jmin] = i;
            else sfree[nf++] = i;
        }
        snfree = nf;
    }
    __syncwarp();
    const int nfree = snfree;

    const float* Cbase = g_costT + (size_t)b * GG * QQ;

    for (int fi = 0; fi < nfree; fi++) {
        const int i = sfree[fi];
        // reset minv' for owned columns (v persists)
#pragma unroll
        for (int s = 0; s < SLOTS; s++) {
            int j = 1 + lane + (s << 5);
            if (j <= m) svm[j].y = 1e30f;
        }
        if (lane == 0) sp[0] = i;
        __syncwarp();

        int j0 = 0;       // uniform across warp
        float D = 0.0f;
        int cnt = 0;

        while (true) {
            const int i0 = sp[j0];            // uniform LDS broadcast
            const float ueff = su[i0] - D;
            if (lane == 0) { susedList[cnt] = j0; sDused[cnt] = D; }
            if (j0 > 0 && (((j0 - 1) & 31) == lane)) svm[j0].y = FNAN; // mark used
            cnt++;

            const float* __restrict__ Crow = Cbase + (size_t)(i0 - 1) * QQ;

            // batched loads: full MLP, one L2 round trip
            float c[SLOTS];
#pragma unroll
            for (int s = 0; s < SLOTS; s++) {
                int j = 1 + lane + (s << 5);
                c[s] = (j <= m) ? __ldg(&Crow[j - 1]) : 1e30f;
            }

            // compute pass against owned shared state
            float lmin = 1e30f;
            int lj = m + 1;
#pragma unroll
            for (int s = 0; s < SLOTS; s++) {
                int j = 1 + lane + (s << 5);
                if (j <= m) {
                    float2 vm = svm[j];
                    float cur = c[s] - ueff - vm.x;
                    float mv = vm.y;               // NaN if used
                    if (cur < mv) {                 // false when mv is NaN
                        mv = cur;
                        svm[j].y = cur;
                        sway[j] = j0;
                    }
                    if (mv < lmin) { lmin = mv; lj = j; }  // false when NaN
                }
            }
            // warp (value, index) min-reduce; tie -> smaller index
#pragma unroll
            for (int off = 16; off; off >>= 1) {
                float ov = __shfl_down_sync(0xffffffffu, lmin, off);
                int   oi = __shfl_down_sync(0xffffffffu, lj, off);
                if (ov < lmin || (ov == lmin && oi < lj)) { lmin = ov; lj = oi; }
            }
            D  = __shfl_sync(0xffffffffu, lmin, 0);  // new cumulative offset
            j0 = __shfl_sync(0xffffffffu, lj, 0);
            if (sp[j0] == 0) break;
        }

        // commit duals over used columns (distinct rows & cols -> race-free)
        __syncwarp();
        for (int t = lane; t < cnt; t += 32) {
            int j = susedList[t];
            float dd = D - sDused[t];
            su[sp[j]] += dd;
            if (j != 0) svm[j].x -= dd;
        }
        __syncwarp();
        if (lane == 0) {
            int jj = j0;
            while (jj != 0) {
                int jn = sway[jj];
                sp[jj] = sp[jn];
                jj = jn;
            }
        }
        __syncwarp();
    }

    for (int j = lane + 1; j <= m; j += 32) {
        int r = sp[j];
        g_match[b * QQ + (j - 1)] = (r > 0) ? g_vlist[b * GG + (r - 1)] : -1;
    }
    if (lane == 0) atomicAdd(&g_nmatched, n);
}

__global__ void loss_kernel(const float* __restrict__ logits,
                            const float* __restrict__ pboxes,
                            const int*   __restrict__ gtc,
                            const float* __restrict__ gboxes) {
    int idx = blockIdx.x * blockDim.x + threadIdx.x;
    double nllw = 0.0, wsum = 0.0, l1acc = 0.0, glacc = 0.0;

    if (idx < BB * QQ) {
        int b = idx / QQ;
        const float* lg = logits + (size_t)idx * NC1;
        float mx = lg[0];
#pragma unroll
        for (int c = 1; c < NC1; c++) mx = fmaxf(mx, lg[c]);
        float s = 0.f;
#pragma unroll
        for (int c = 0; c < NC1; c++) s += expf(lg[c] - mx);
        float logZ = mx + logf(s);

        int mg = g_match[idx];
        int t = (mg >= 0) ? gtc[b * GG + mg] : NC;
        float logp = lg[t] - logZ;
        float wt = (t == NC) ? 0.1f : 1.0f;
        nllw = (double)(wt * (-logp));
        wsum = (double)wt;

        if (mg >= 0) {
            const float* pb = pboxes + (size_t)idx * 4;
            const float* gb = gboxes + ((size_t)(b * GG + mg)) * 4;
            float pcx = pb[0], pcy = pb[1], pw = pb[2], ph = pb[3];
            float gcx = gb[0], gcy = gb[1], gw = gb[2], gh = gb[3];
            l1acc = (double)(fabsf(pcx - gcx) + fabsf(pcy - gcy) +
                             fabsf(pw - gw) + fabsf(ph - gh));
            float px0 = pcx - pw * 0.5f, py0 = pcy - ph * 0.5f;
            float px1 = pcx + pw * 0.5f, py1 = pcy + ph * 0.5f;
            float gx0 = gcx - gw * 0.5f, gy0 = gcy - gh * 0.5f;
            float gx1 = gcx + gw * 0.5f, gy1 = gcy + gh * 0.5f;
            float pa = fmaxf(px1 - px0, 0.f) * fmaxf(py1 - py0, 0.f);
            float ga = fmaxf(gx1 - gx0, 0.f) * fmaxf(gy1 - gy0, 0.f);
            float ltx = fmaxf(px0, gx0), lty = fmaxf(py0, gy0);
            float rbx = fminf(px1, gx1), rby = fminf(py1, gy1);
            float iw = fmaxf(rbx - ltx, 0.f), ih = fmaxf(rby - lty, 0.f);
            float inter = iw * ih;
            float uni = pa + ga - inter;
            float iou = inter / fmaxf(uni, 1e-6f);
            float ex0 = fminf(px0, gx0), ey0 = fminf(py0, gy0);
            float ex1 = fmaxf(px1, gx1), ey1 = fmaxf(py1, gy1);
            float ew = fmaxf(ex1 - ex0, 0.f), eh = fmaxf(ey1 - ey0, 0.f);
            float enc = ew * eh;
            float giou = iou - (enc - uni) / fmaxf(enc, 1e-6f);
            glacc = (double)(1.0f - giou);
        }
    }

    __shared__ double s1[256], s2[256], s3[256], s4[256];
    int tid = threadIdx.x;
    s1[tid] = nllw; s2[tid] = wsum; s3[tid] = l1acc; s4[tid] = glacc;
    __syncthreads();
#pragma unroll
    for (int s = 128; s > 0; s >>= 1) {
        if (tid < s) {
            s1[tid] += s1[tid + s];
            s2[tid] += s2[tid + s];
            s3[tid] += s3[tid + s];
            s4[tid] += s4[tid + s];
        }
        __syncthreads();
    }
    if (tid == 0) {
        atomicAdd(&g_cls_num, s1[0]);
        atomicAdd(&g_cls_den, s2[0]);
        atomicAdd(&g_l1, s3[0]);
        atomicAdd(&g_gl, s4[0]);
    }
}

__global__ void finalize_kernel(float* __restrict__ out) {
    if (threadIdx.x == 0) {
        int nm = g_nmatched;
        if (nm < 1) nm = 1;
        double nmd = (double)nm;
        double cls = g_cls_num / g_cls_den;
        out[0] = (float)(2.0 * cls + 5.0 * g_l1 / nmd + 2.0 * g_gl / nmd);
    }
}

extern "C" void kernel_launch(void* const* d_in, const int* in_sizes, int n_in,
                              void* d_out, int out_size) {
    const float* pred_logits = (const float*)d_in[0];
    const float* pred_boxes  = (const float*)d_in[1];
    const int*   gt_classes  = (const int*)d_in[2];
    const float* gt_boxes    = (const float*)d_in[3];
    float* out = (float*)d_out;

    init_kernel<<<1, 32>>>();
    prep_kernel<<<BB, 32>>>(gt_classes);

    dim3 cgrid((QQ + 127) / 128, BB);
    cost_kernel<<<cgrid, 128>>>(pred_logits, pred_boxes, gt_classes, gt_boxes);

    dim3 rgrid(GG, BB);
    rowmin_kernel<<<rgrid, 256>>>();

    jv_kernel<<<BB, 32>>>();

    int total = BB * QQ;
    loss_kernel<<<(total + 255) / 256, 256>>>(pred_logits, pred_boxes,
                                              gt_classes, gt_boxes);
    finalize_kernel<<<1, 32>>>(out);
}